// round 3
// baseline (speedup 1.0000x reference)
#include <cuda_runtime.h>

// CRF NLL, prob-domain forward with chunked renormalization.
// B=64, S=512, T=64 (62 tags + START=62 + END=63).
// R3: 2 batches per CTA (512 threads = 2 independent 256-thread groups,
//     named barriers) so the two chains' serial tails hide each other.
//
// Inputs: d_in[0] feats f32 [B,S,T], d_in[1] transitions f32 [T,T],
//         d_in[2] mask i32 [B,S] (contiguous prefix), d_in[3] tags i32 [B,S]
// Output: f32 scalar sum_b (forward_b - gold_b)

#define B_    64
#define S_    512
#define T_    64
#define CHUNK 8
#define NG    2      // batch-groups per CTA
#define GSZ   256    // threads per group

__device__ float g_res[B_];

// group barrier: named barrier (id = grp+1), 256 threads
#define GBAR(grp) asm volatile("bar.sync %0, %1;" :: "r"((grp) + 1), "n"(GSZ) : "memory")

__global__ __launch_bounds__(NG * GSZ, 1) void crf_forward_kernel(
    const float* __restrict__ feats,
    const float* __restrict__ trans,
    const int*   __restrict__ mask,
    const int*   __restrict__ tags)
{
    __shared__ float trans_sh[T_ * T_];
    __shared__ float p_sh[NG][2][T_];
    __shared__ float f_sh[NG][CHUNK][T_];
    __shared__ int   tags_sh[NG][S_];
    __shared__ float redg[NG][8];
    __shared__ float redf[NG][2];
    __shared__ int   redi[NG][8];

    const int tid  = threadIdx.x;
    const int grp  = tid >> 8;           // 0..1 : batch group
    const int gt   = tid & 255;          // thread within group
    const int lane = tid & 31;
    const int gw   = gt >> 5;            // warp within group 0..7
    const int seg  = lane >> 3;          // 0..3 : i-segment of 16
    const int j    = (gw << 3) | (lane & 7);  // 0..63 : state column
    const int r    = gt >> 6;            // 0..3 : staging row group
    const int col  = gt & 63;            // staging column

    const int b = blockIdx.x * NG + grp;

    const float* fb    = feats + (size_t)b * S_ * T_;
    const int*   maskb = mask  + b * S_;
    const int*   tagsb = tags  + b * S_;

    // ---- stage transitions (all 512 threads, coalesced float4) ----
    {
        const float4* t4 = (const float4*)trans;
        float4*       s4 = (float4*)trans_sh;
        #pragma unroll
        for (int i = 0; i < 2; ++i) s4[i * 512 + tid] = t4[i * 512 + tid];
    }
    // ---- tags + length (per group) ----
    int lenp = 0;
    #pragma unroll
    for (int k = 0; k < 2; ++k) {
        tags_sh[grp][k * 256 + gt] = tagsb[k * 256 + gt];
        lenp += maskb[k * 256 + gt];
    }
    #pragma unroll
    for (int o = 16; o; o >>= 1) lenp += __shfl_xor_sync(0xffffffffu, lenp, o);
    if (lane == 0) redi[grp][gw] = lenp;
    __syncthreads();   // trans_sh, tags_sh, redi visible block-wide
    int len = 0;
    #pragma unroll
    for (int w = 0; w < 8; ++w) len += redi[grp][w];

    // ---- gold path score (per group) ----
    float g = 0.f;
    #pragma unroll
    for (int kk = 0; kk < 2; ++kk) {
        int s = kk * 256 + gt;
        if (s < len) {
            int tg = tags_sh[grp][s];
            int pv = s ? tags_sh[grp][s - 1] : (T_ - 2);
            g += fb[s * T_ + tg] + trans_sh[pv * T_ + tg];
        }
    }
    if (gt == 0) g += trans_sh[tags_sh[grp][len - 1] * T_ + (T_ - 1)];
    #pragma unroll
    for (int o = 16; o; o >>= 1) g += __shfl_xor_sync(0xffffffffu, g, o);
    if (lane == 0) redg[grp][gw] = g;

    // ---- E segment into registers: e[rr] = exp(trans[seg*16+rr][j]) ----
    float e[16];
    #pragma unroll
    for (int rr = 0; rr < 16; ++rr)
        e[rr] = __expf(trans_sh[(seg * 16 + rr) * T_ + j]);

    // ---- init p_0 ----
    if (gt < T_)
        p_sh[grp][0][gt] = __expf(fb[gt] + trans_sh[(T_ - 2) * T_ + gt]);

    // ---- prefetch first chunk's feats (rows 1..8) ----
    int c = 1;
    float fr0, fr1;
    {
        int r0 = min(c + r,     S_ - 1);
        int r1 = min(c + r + 4, S_ - 1);
        fr0 = fb[r0 * T_ + col];
        fr1 = fb[r1 * T_ + col];
    }
    GBAR(grp);   // p_sh, redg visible within group

    // ---- forward recurrence ----
    int   cur    = 0;
    float logacc = 0.f;

    while (c < len) {
        // stage exp(f) for this chunk from prefetched regs
        f_sh[grp][r][col]     = __expf(fr0);
        f_sh[grp][r + 4][col] = __expf(fr1);

        // prefetch next chunk
        int nc = c + CHUNK;
        if (nc < S_) {
            int r0 = min(nc + r,     S_ - 1);
            int r1 = min(nc + r + 4, S_ - 1);
            fr0 = fb[r0 * T_ + col];
            fr1 = fb[r1 * T_ + col];
        }

        // renormalize: z = sum(p) (broadcast LDS, redundant per-thread tree)
        float z;
        {
            const float4* pv4 = (const float4*)p_sh[grp][cur];
            float z0 = 0.f, z1 = 0.f, z2 = 0.f, z3 = 0.f;
            #pragma unroll
            for (int i = 0; i < 16; i += 4) {
                float4 q0 = pv4[i],     q1 = pv4[i + 1];
                float4 q2 = pv4[i + 2], q3 = pv4[i + 3];
                z0 += (q0.x + q0.y) + (q0.z + q0.w);
                z1 += (q1.x + q1.y) + (q1.z + q1.w);
                z2 += (q2.x + q2.y) + (q2.z + q2.w);
                z3 += (q3.x + q3.y) + (q3.z + q3.w);
            }
            z = (z0 + z1) + (z2 + z3);
        }
        float scale = __fdividef(1.0f, z);
        logacc += __logf(z);

        const int cnt = min(CHUNK, len - c);
        GBAR(grp);   // f_sh visible; all group reads of p done

        #pragma unroll
        for (int k = 0; k < CHUNK; ++k) {
            if (k >= cnt) break;   // cnt uniform across group
            float fk = f_sh[grp][k][j];   // off the post-shfl critical path
            const float4* pp4 = (const float4*)(p_sh[grp][cur] + (seg << 4));
            float a0 = 0.f, a1 = 0.f, a2 = 0.f, a3 = 0.f;
            #pragma unroll
            for (int i = 0; i < 4; ++i) {
                float4 pp = pp4[i];
                a0 = fmaf(pp.x, e[4 * i + 0], a0);
                a1 = fmaf(pp.y, e[4 * i + 1], a1);
                a2 = fmaf(pp.z, e[4 * i + 2], a2);
                a3 = fmaf(pp.w, e[4 * i + 3], a3);
            }
            float v = (a0 + a1) + (a2 + a3);
            v += __shfl_xor_sync(0xffffffffu, v, 8);
            v += __shfl_xor_sync(0xffffffffu, v, 16);
            float q = v * fk;
            if (k == 0) q *= scale;
            if (seg == 0) p_sh[grp][cur ^ 1][j] = q;
            GBAR(grp);
            cur ^= 1;
        }
        c += CHUNK;
    }

    // ---- final transition into END ----
    if (gt < T_) {
        float v = p_sh[grp][cur][gt] * __expf(trans_sh[gt * T_ + (T_ - 1)]);
        #pragma unroll
        for (int o = 16; o; o >>= 1) v += __shfl_xor_sync(0xffffffffu, v, o);
        if (lane == 0) redf[grp][gw] = v;
    }
    GBAR(grp);
    if (gt == 0) {
        float forward = logacc + __logf(redf[grp][0] + redf[grp][1]);
        float gold = 0.f;
        #pragma unroll
        for (int w = 0; w < 8; ++w) gold += redg[grp][w];
        g_res[b] = forward - gold;
    }
}

__global__ void crf_reduce_kernel(float* __restrict__ out)
{
    const int tid  = threadIdx.x;
    const int lane = tid & 31;
    const int warp = tid >> 5;
    __shared__ float sh[2];

    float v = g_res[tid];
    #pragma unroll
    for (int o = 16; o; o >>= 1) v += __shfl_xor_sync(0xffffffffu, v, o);
    if (lane == 0) sh[warp] = v;
    __syncthreads();
    if (tid == 0) out[0] = sh[0] + sh[1];
}

extern "C" void kernel_launch(void* const* d_in, const int* in_sizes, int n_in,
                              void* d_out, int out_size)
{
    const float* feats = (const float*)d_in[0];
    const float* trans = (const float*)d_in[1];
    const int*   mask  = (const int*)d_in[2];
    const int*   tags  = (const int*)d_in[3];
    float* out = (float*)d_out;

    crf_forward_kernel<<<B_ / NG, NG * GSZ>>>(feats, trans, mask, tags);
    crf_reduce_kernel<<<1, 64>>>(out);
}